// round 15
// baseline (speedup 1.0000x reference)
#include <cuda_runtime.h>
#include <cuda_fp16.h>
#include <cstdint>
#include <cstddef>

#define BATCH   8
#define NODES   2048
#define IN_DIM  64
#define HEADS   4
#define UDIM    1024
#define NNB     32

// fp16 hi/lo split operands (produced by qkgemm)
__device__ __half g_Qh[BATCH * NODES * 256];   // q rows (pre-scaled): per head [hi32|lo32]
__device__ __half g_Kh[BATCH * UDIM  * 256];
__device__ float  g_S [BATCH * NODES * UDIM];  // scores

#define CP16(dst, src) asm volatile("cp.async.cg.shared.global [%0], [%1], 16;" :: "r"(dst), "l"(src))
#define CPCOMMIT()     asm volatile("cp.async.commit_group;" ::: "memory")
#define CPWAIT0()      asm volatile("cp.async.wait_group 0;" ::: "memory")

__device__ __forceinline__ uint32_t smem_u32(const void* p) {
    uint32_t a;
    asm("{ .reg .u64 t; cvta.to.shared.u64 t, %1; cvt.u32.u64 %0, t; }" : "=r"(a) : "l"(p));
    return a;
}
__device__ __forceinline__ void mma_f16(float* c, const uint32_t* a, const uint32_t* b) {
    asm volatile("mma.sync.aligned.m16n8k16.row.col.f32.f16.f16.f32 "
        "{%0,%1,%2,%3}, {%4,%5,%6,%7}, {%8,%9}, {%0,%1,%2,%3};"
        : "+f"(c[0]), "+f"(c[1]), "+f"(c[2]), "+f"(c[3])
        : "r"(a[0]), "r"(a[1]), "r"(a[2]), "r"(a[3]), "r"(b[0]), "r"(b[1]));
}
__device__ __forceinline__ void ldsm_x4(uint32_t* r, uint32_t addr) {
    asm volatile("ldmatrix.sync.aligned.m8n8.x4.shared.b16 {%0,%1,%2,%3}, [%4];"
        : "=r"(r[0]), "=r"(r[1]), "=r"(r[2]), "=r"(r[3]) : "r"(addr));
}
__device__ __forceinline__ void split2(float v0, float v1, uint32_t& hp, uint32_t& lp) {
    __half h0 = __float2half_rn(v0), h1 = __float2half_rn(v1);
    __half l0 = __float2half_rn(v0 - __half2float(h0));
    __half l1 = __float2half_rn(v1 - __half2float(h1));
    hp = ((uint32_t)__half_as_ushort(h1) << 16) | __half_as_ushort(h0);
    lp = ((uint32_t)__half_as_ushort(l1) << 16) | __half_as_ushort(l0);
}
__device__ __forceinline__ float key2val(unsigned k) {
    unsigned u = (k & 0x80000000u) ? (k ^ 0x80000000u) : ~k;
    return __uint_as_float(u);
}

// ---------------------------------------------------------------------------
// Kernel 1: QK projection via HMMA with fused fp32->split-fp16 staging
// (R14-proven).
// ---------------------------------------------------------------------------
#define XROW    272
#define QG_SMX  0
#define QG_SMW  34816
#define QG_SB   69632
#define QG_SMEM 70144

__global__ void __launch_bounds__(256) qkgemm_kernel(
    const float* __restrict__ x,
    const float* __restrict__ Wq, const float* __restrict__ bq,
    const float* __restrict__ Wk, const float* __restrict__ bk)
{
    extern __shared__ __align__(16) char sm[];
    const uint32_t smb = smem_u32(sm);
    const int tid = threadIdx.x, lane = tid & 31, wid = tid >> 5;

    const bool isQ = (blockIdx.x < 128);
    int b, n0; const float* bias; const float* W; float scale;
    if (isQ) { b = blockIdx.x >> 4;            n0 = (blockIdx.x & 15) << 7; bias = bq; W = Wq; scale = 0.17677669529663687f; }
    else     { int id = blockIdx.x - 128; b = id >> 3; n0 = (id & 7) << 7;  bias = bk; W = Wk; scale = 1.0f; }

    {
        const float* xsrc = x + ((size_t)(b * NODES + n0)) * IN_DIM;
#pragma unroll
        for (int it = 0; it < 8; it++) {
            const int idx = it * 1024 + tid * 4;
            float4 v = *(const float4*)(xsrc + idx);
            const int row = idx >> 6, k = idx & 63;
            uint32_t hp0, lp0, hp1, lp1;
            split2(v.x, v.y, hp0, lp0);
            split2(v.z, v.w, hp1, lp1);
            char* dst = sm + QG_SMX + row * XROW + k * 2;
            *(uint32_t*)dst         = hp0;  *(uint32_t*)(dst + 4)   = hp1;
            *(uint32_t*)(dst + 128) = lp0;  *(uint32_t*)(dst + 132) = lp1;
        }
#pragma unroll
        for (int it = 0; it < 8; it++) {
            const int idx = it * 1024 + tid * 4;
            float4 v = *(const float4*)(W + idx);
            const int row = idx >> 6, k = idx & 63;
            uint32_t hp0, lp0, hp1, lp1;
            split2(v.x, v.y, hp0, lp0);
            split2(v.z, v.w, hp1, lp1);
            char* dst = sm + QG_SMW + row * XROW + k * 2;
            *(uint32_t*)dst         = hp0;  *(uint32_t*)(dst + 4)   = hp1;
            *(uint32_t*)(dst + 128) = lp0;  *(uint32_t*)(dst + 132) = lp1;
        }
    }
    if (tid < 128) ((float*)(sm + QG_SB))[tid] = bias[tid] * scale;
    __syncthreads();

    const int r0 = wid << 4;
    uint32_t aF[4][2][4];
    {
        const uint32_t qb = smb + QG_SMX + (r0 + (lane & 15)) * XROW + ((lane >> 4) << 4);
#pragma unroll
        for (int s = 0; s < 4; s++)
#pragma unroll
            for (int p = 0; p < 2; p++)
                ldsm_x4(aF[s][p], qb + p * 128 + s * 32);
    }

    float acc[16][4];
#pragma unroll
    for (int j = 0; j < 16; j++)
#pragma unroll
        for (int q = 0; q < 4; q++) acc[j][q] = 0.f;

#pragma unroll
    for (int j = 0; j < 16; j++) {
        const uint32_t kb = smb + QG_SMW + (j * 8 + (lane & 7)) * XROW + ((lane >> 3) << 4);
        uint32_t bh0[4], bh1[4], bl0[4], bl1[4];
        ldsm_x4(bh0, kb);
        ldsm_x4(bh1, kb + 64);
        ldsm_x4(bl0, kb + 128);
        ldsm_x4(bl1, kb + 192);
#pragma unroll
        for (int s = 0; s < 4; s++) {
            const uint32_t* bh = (s < 2) ? (bh0 + 2 * s) : (bh1 + 2 * (s - 2));
            const uint32_t* bl = (s < 2) ? (bl0 + 2 * s) : (bl1 + 2 * (s - 2));
            mma_f16(acc[j], aF[s][0], bh);
            mma_f16(acc[j], aF[s][0], bl);
            mma_f16(acc[j], aF[s][1], bh);
        }
    }

    const float* sb = (const float*)(sm + QG_SB);
    const int ra = n0 + r0 + (lane >> 2);
    __half* gout = isQ ? g_Qh : g_Kh;
    const size_t base = ((size_t)(b * (isQ ? NODES : UDIM) + ra)) * 256;
#pragma unroll
    for (int j = 0; j < 16; j++) {
        const int c0 = j * 8 + (lane & 3) * 2;
        const float b0 = sb[c0], b1 = sb[c0 + 1];
        const int o = ((c0 >> 5) << 6) + (c0 & 31);
#pragma unroll
        for (int rr = 0; rr < 2; rr++) {
            float v0 = fmaf(acc[j][2 * rr],     scale, b0);
            float v1 = fmaf(acc[j][2 * rr + 1], scale, b1);
            uint32_t hp, lp;
            split2(v0, v1, hp, lp);
            __half* dst = gout + base + (size_t)rr * 8 * 256 + o;
            *(uint32_t*)dst        = hp;
            *(uint32_t*)(dst + 32) = lp;
        }
    }
}

// ---------------------------------------------------------------------------
// Kernel 2: fused score + top-32 kernel. 256 blocks x 64 n-rows, 2 blocks/SM.
// Mainloop: 16 chunks of 64u (R14-proven), zero-fill hidden under MMA.
// Tail: in-block radix select on the block's own (L2-hot) 64 score rows;
// select scratch aliases the dead K double-buffer.
// ---------------------------------------------------------------------------
#define SKROW   528
#define SMQ     0                      // 64*528 = 33792
#define SMK     33792                  // 2 * 64*528 = 67584
#define KBUF    (64 * SKROW)
#define SC_SMEM 101376
// tail scratch (aliases SMK region, dead after mainloop)
#define TK_H    SMK                    // hist: 8 x 256 u32 = 8192
#define TK_T    (SMK + 8192)           // ties: 8 x 64 u32  = 2048
#define TK_F    (SMK + 10240)          // found: 8 x 2 u32
#define TK_C    (SMK + 10304)          // cnt: 8 u32

__device__ __forceinline__ void fillK_async(uint32_t smb, int b, int ustart, int buf, int tid) {
    const char* src = (const char*)(g_Kh + ((size_t)(b * UDIM + ustart)) * 256);
    const uint32_t dst = smb + SMK + buf * KBUF;
#pragma unroll
    for (int it = 0; it < 8; it++) {
        int idx = it * 256 + tid;
        int row = idx >> 5, j = idx & 31;
        CP16(dst + row * SKROW + j * 16, src + row * 512 + j * 16);
    }
}

__global__ void __launch_bounds__(256, 2) score_kernel(
    const float* __restrict__ mlp_w, const float* __restrict__ mlp_b,
    float* __restrict__ out)
{
    extern __shared__ __align__(16) char sm[];
    const uint32_t smb = smem_u32(sm);
    const int tid = threadIdx.x, lane = tid & 31, wid = tid >> 5;
    const int wr0 = (wid & 3) << 4;
    const int uw0 = (wid >> 2) << 4;
    const int b  = blockIdx.x >> 5;
    const int n0 = (blockIdx.x & 31) << 6;

    {
        const char* qsrc = (const char*)(g_Qh + ((size_t)(b * NODES + n0)) * 256);
#pragma unroll
        for (int it = 0; it < 8; it++) {
            int idx = it * 256 + tid;
            int row = idx >> 5, j = idx & 31;
            CP16(smb + SMQ + row * SKROW + j * 16, qsrc + row * 512 + j * 16);
        }
    }
    fillK_async(smb, b, 0, 0, tid);
    CPCOMMIT();

    float mm[4][4], mb_[4];
#pragma unroll
    for (int o = 0; o < 4; o++) {
        mb_[o] = mlp_b[o];
#pragma unroll
        for (int h = 0; h < 4; h++) mm[o][h] = mlp_w[o * 4 + h];
    }
    CPWAIT0();
    __syncthreads();

    uint32_t aF[4][2][2][4];
    {
        const char* qb = sm + SMQ + (wr0 + (lane >> 2)) * SKROW;
#pragma unroll
        for (int h = 0; h < 4; h++)
#pragma unroll
            for (int p = 0; p < 2; p++)
#pragma unroll
                for (int s = 0; s < 2; s++) {
                    int off = (h * 64 + p * 32 + s * 16 + (lane & 3) * 2) * 2;
                    aF[h][p][s][0] = *(const uint32_t*)(qb + off);
                    aF[h][p][s][1] = *(const uint32_t*)(qb + off + 8 * SKROW);
                    aF[h][p][s][2] = *(const uint32_t*)(qb + off + 16);
                    aF[h][p][s][3] = *(const uint32_t*)(qb + off + 8 * SKROW + 16);
                }
    }

    for (int ck = 0; ck < 16; ck++) {
        const int buf = ck & 1;
        CPWAIT0();
        __syncthreads();
        if (ck + 1 < 16) { fillK_async(smb, b, (ck + 1) * 64, buf ^ 1, tid); CPCOMMIT(); }

        // zero-fill 4 of this block's 64 output rows (streaming, hidden)
        {
            const int zr = ck * 4 + (tid >> 6);
            float4* zrow = (float4*)(out + ((size_t)(b * NODES + n0 + zr)) * NODES);
            const float4 z4 = make_float4(0.f, 0.f, 0.f, 0.f);
#pragma unroll
            for (int i = 0; i < 8; i++) __stcs(zrow + i * 64 + (tid & 63), z4);
        }

#pragma unroll
        for (int h2 = 0; h2 < 2; h2++) {
            float acc[2][4][4];
#pragma unroll
            for (int ut = 0; ut < 2; ut++)
#pragma unroll
                for (int h = 0; h < 4; h++)
#pragma unroll
                    for (int q = 0; q < 4; q++) acc[ut][h][q] = 0.f;

#pragma unroll
            for (int ut = 0; ut < 2; ut++) {
                const uint32_t kb = smb + SMK + buf * KBUF +
                                    (h2 * 32 + uw0 + ut * 8 + (lane & 7)) * SKROW +
                                    ((lane >> 3) << 4);
#pragma unroll
                for (int h = 0; h < 4; h++) {
                    uint32_t bh[4], bl[4];
                    ldsm_x4(bh, kb + h * 128);
                    ldsm_x4(bl, kb + h * 128 + 64);
#pragma unroll
                    for (int s = 0; s < 2; s++) {
                        mma_f16(acc[ut][h], aF[h][0][s], bh + 2 * s);   // hh
                        mma_f16(acc[ut][h], aF[h][0][s], bl + 2 * s);   // hl
                        mma_f16(acc[ut][h], aF[h][1][s], bh + 2 * s);   // lh
                    }
                }
            }

            const int u0 = ck * 64 + h2 * 32;
#pragma unroll
            for (int ut = 0; ut < 2; ut++) {
                float s_[4];
#pragma unroll
                for (int q = 0; q < 4; q++) {
                    float a0 = acc[ut][0][q], a1 = acc[ut][1][q];
                    float a2 = acc[ut][2][q], a3 = acc[ut][3][q];
                    float s = a0 + a1 + a2 + a3;
#pragma unroll
                    for (int o = 0; o < 4; o++) {
                        float z = fmaf(mm[o][0], a0, fmaf(mm[o][1], a1,
                                  fmaf(mm[o][2], a2, fmaf(mm[o][3], a3, mb_[o]))));
                        s += fmaxf(z, 0.f);
                    }
                    s_[q] = s;
                }
                float* sg = g_S + ((size_t)(b * NODES + n0 + wr0 + (lane >> 2))) * UDIM
                            + u0 + uw0 + ut * 8 + (lane & 3) * 2;
                *(float2*)sg              = make_float2(s_[0], s_[1]);
                *(float2*)(sg + 8 * UDIM) = make_float2(s_[2], s_[3]);
            }
        }
    }
    __syncthreads();   // all score writes + zero-fill visible block-wide

    // ---- tail: top-32 radix select on this block's 64 rows (8 per warp) ----
    unsigned* hist  = (unsigned*)(sm + TK_H) + wid * 256;
    unsigned* ties  = (unsigned*)(sm + TK_T) + wid * 64;
    unsigned* found = (unsigned*)(sm + TK_F) + wid * 2;
    unsigned* tcnt  = (unsigned*)(sm + TK_C) + wid;

    for (int rr = 0; rr < 8; rr++) {
        const int row = wid * 8 + rr;
        const float4* srow4 = (const float4*)(g_S + ((size_t)(b * NODES + n0 + row)) * UDIM);
        unsigned keys[32];
#pragma unroll
        for (int i = 0; i < 8; i++) {
            float4 v = srow4[i * 32 + lane];
            const float f[4] = {v.x, v.y, v.z, v.w};
#pragma unroll
            for (int c = 0; c < 4; c++) {
                unsigned u = __float_as_uint(f[c]);
                keys[i * 4 + c] = u ^ (((unsigned)((int)u >> 31)) | 0x80000000u);
            }
        }

        unsigned prefix = 0;
        int needed = NNB;
        for (int shift = 24; shift >= 0; shift -= 8) {
            for (int t = lane; t < 256; t += 32) hist[t] = 0;
            __syncwarp();
            const unsigned hm = (shift == 24) ? 0u : (0xFFFFFFFFu << (shift + 8));
#pragma unroll
            for (int j = 0; j < 32; j++)
                if (((keys[j] ^ prefix) & hm) == 0)
                    atomicAdd(&hist[(keys[j] >> shift) & 255], 1u);
            __syncwarp();
            unsigned s = 0;
#pragma unroll
            for (int t = 0; t < 8; t++) s += hist[lane * 8 + t];
            unsigned rs = s;
#pragma unroll
            for (int off = 1; off < 32; off <<= 1) {
                unsigned v = __shfl_down_sync(0xffffffffu, rs, off);
                if (lane + off < 32) rs += v;
            }
            unsigned acc2 = rs - s;
            for (int t = 7; t >= 0; t--) {
                unsigned c = hist[lane * 8 + t];
                if ((int)acc2 < needed && needed <= (int)(acc2 + c)) {
                    found[0] = (unsigned)(lane * 8 + t);
                    found[1] = acc2;
                }
                acc2 += c;
            }
            __syncwarp();
            prefix |= found[0] << shift;
            needed -= (int)found[1];
            __syncwarp();
        }

        float* orow = out + ((size_t)(b * NODES + n0 + row)) * (size_t)NODES;
        if (lane == 0) *tcnt = 0;
        __syncwarp();
#pragma unroll
        for (int j = 0; j < 32; j++) {
            const unsigned elem = (unsigned)((j >> 2) * 128 + lane * 4 + (j & 3));
            if (keys[j] > prefix) orow[elem] = key2val(keys[j]);
            else if (keys[j] == prefix) {
                unsigned p = atomicAdd(tcnt, 1u);
                if (p < 64) ties[p] = elem;
            }
        }
        __syncwarp();
        if (lane == 0) {
            int cnt = *tcnt < 64 ? (int)*tcnt : 64;
            float kval = key2val(prefix);
            for (int e = 0; e < needed; e++) {
                int bi = -1; unsigned bidx = 0xFFFFFFFFu;
                for (int t = 0; t < cnt; t++)
                    if (ties[t] < bidx) { bidx = ties[t]; bi = t; }
                if (bi >= 0) { orow[bidx] = kval; ties[bi] = 0xFFFFFFFFu; }
            }
        }
        __syncwarp();
    }
}

// ---------------------------------------------------------------------------
extern "C" void kernel_launch(void* const* d_in, const int* in_sizes, int n_in,
                              void* d_out, int out_size)
{
    const float* x     = (const float*)d_in[0];
    const float* Wq    = (const float*)d_in[1];
    const float* bq    = (const float*)d_in[2];
    const float* Wk    = (const float*)d_in[3];
    const float* bk    = (const float*)d_in[4];
    const float* mlp_w = (const float*)d_in[5];
    const float* mlp_b = (const float*)d_in[6];

    float* out = (float*)d_out;

    cudaFuncSetAttribute(qkgemm_kernel,
                         cudaFuncAttributeMaxDynamicSharedMemorySize, QG_SMEM);
    qkgemm_kernel<<<192, 256, QG_SMEM>>>(x, Wq, bq, Wk, bk);

    cudaFuncSetAttribute(score_kernel,
                         cudaFuncAttributeMaxDynamicSharedMemorySize, SC_SMEM);
    score_kernel<<<256, 256, SC_SMEM>>>(mlp_w, mlp_b, out);
}

// round 16
// speedup vs baseline: 1.2296x; 1.2296x over previous
#include <cuda_runtime.h>
#include <cuda_fp16.h>
#include <cstdint>
#include <cstddef>

#define BATCH   8
#define NODES   2048
#define IN_DIM  64
#define HEADS   4
#define UDIM    1024
#define NNB     32

// fp16 hi/lo split operands (produced by qkgemm)
__device__ __half g_Qh[BATCH * NODES * 256];   // q rows (pre-scaled): per head [hi32|lo32]
__device__ __half g_Kh[BATCH * UDIM  * 256];
__device__ float  g_S [BATCH * NODES * UDIM];  // scores

#define CP16(dst, src) asm volatile("cp.async.cg.shared.global [%0], [%1], 16;" :: "r"(dst), "l"(src))
#define CPCOMMIT()     asm volatile("cp.async.commit_group;" ::: "memory")
#define CPWAIT0()      asm volatile("cp.async.wait_group 0;" ::: "memory")

__device__ __forceinline__ uint32_t smem_u32(const void* p) {
    uint32_t a;
    asm("{ .reg .u64 t; cvta.to.shared.u64 t, %1; cvt.u32.u64 %0, t; }" : "=r"(a) : "l"(p));
    return a;
}
__device__ __forceinline__ void mma_f16(float* c, const uint32_t* a, const uint32_t* b) {
    asm volatile("mma.sync.aligned.m16n8k16.row.col.f32.f16.f16.f32 "
        "{%0,%1,%2,%3}, {%4,%5,%6,%7}, {%8,%9}, {%0,%1,%2,%3};"
        : "+f"(c[0]), "+f"(c[1]), "+f"(c[2]), "+f"(c[3])
        : "r"(a[0]), "r"(a[1]), "r"(a[2]), "r"(a[3]), "r"(b[0]), "r"(b[1]));
}
__device__ __forceinline__ void ldsm_x4(uint32_t* r, uint32_t addr) {
    asm volatile("ldmatrix.sync.aligned.m8n8.x4.shared.b16 {%0,%1,%2,%3}, [%4];"
        : "=r"(r[0]), "=r"(r[1]), "=r"(r[2]), "=r"(r[3]) : "r"(addr));
}
__device__ __forceinline__ void split2(float v0, float v1, uint32_t& hp, uint32_t& lp) {
    __half h0 = __float2half_rn(v0), h1 = __float2half_rn(v1);
    __half l0 = __float2half_rn(v0 - __half2float(h0));
    __half l1 = __float2half_rn(v1 - __half2float(h1));
    hp = ((uint32_t)__half_as_ushort(h1) << 16) | __half_as_ushort(h0);
    lp = ((uint32_t)__half_as_ushort(l1) << 16) | __half_as_ushort(l0);
}
__device__ __forceinline__ float key2val(unsigned k) {
    unsigned u = (k & 0x80000000u) ? (k ^ 0x80000000u) : ~k;
    return __uint_as_float(u);
}

// ---------------------------------------------------------------------------
// Kernel 1: QK projection via HMMA, fused fp32->split-fp16 staging.
// 64-row tiles, 2 blocks/SM: blocks [0,256) = Q, [256,384) = K.
// 8 warps = 4 row-groups (16 rows) x 2 j-groups (8 j-tiles = 64 cols).
// ---------------------------------------------------------------------------
#define XROW    272
#define QG_SMX  0                      // 64*272  = 17408
#define QG_SMW  17408                  // 128*272 = 34816
#define QG_SB   52224                  // 512
#define QG_SMEM 52736

__global__ void __launch_bounds__(256, 2) qkgemm_kernel(
    const float* __restrict__ x,
    const float* __restrict__ Wq, const float* __restrict__ bq,
    const float* __restrict__ Wk, const float* __restrict__ bk)
{
    extern __shared__ __align__(16) char sm[];
    const uint32_t smb = smem_u32(sm);
    const int tid = threadIdx.x, lane = tid & 31, wid = tid >> 5;

    const bool isQ = (blockIdx.x < 256);
    int b, n0; const float* bias; const float* W; float scale;
    if (isQ) { b = blockIdx.x >> 5;            n0 = (blockIdx.x & 31) << 6; bias = bq; W = Wq; scale = 0.17677669529663687f; }
    else     { int id = blockIdx.x - 256; b = id >> 4; n0 = (id & 15) << 6;  bias = bk; W = Wk; scale = 1.0f; }

    // fused staging: load fp32, split to [hi64|lo64] fp16 rows in smem
    {
        const float* xsrc = x + ((size_t)(b * NODES + n0)) * IN_DIM;   // 64 x 64
#pragma unroll
        for (int it = 0; it < 4; it++) {
            const int idx = it * 1024 + tid * 4;
            float4 v = *(const float4*)(xsrc + idx);
            const int row = idx >> 6, k = idx & 63;
            uint32_t hp0, lp0, hp1, lp1;
            split2(v.x, v.y, hp0, lp0);
            split2(v.z, v.w, hp1, lp1);
            char* dst = sm + QG_SMX + row * XROW + k * 2;
            *(uint32_t*)dst         = hp0;  *(uint32_t*)(dst + 4)   = hp1;
            *(uint32_t*)(dst + 128) = lp0;  *(uint32_t*)(dst + 132) = lp1;
        }
#pragma unroll
        for (int it = 0; it < 8; it++) {
            const int idx = it * 1024 + tid * 4;
            float4 v = *(const float4*)(W + idx);                       // 128 x 64
            const int row = idx >> 6, k = idx & 63;
            uint32_t hp0, lp0, hp1, lp1;
            split2(v.x, v.y, hp0, lp0);
            split2(v.z, v.w, hp1, lp1);
            char* dst = sm + QG_SMW + row * XROW + k * 2;
            *(uint32_t*)dst         = hp0;  *(uint32_t*)(dst + 4)   = hp1;
            *(uint32_t*)(dst + 128) = lp0;  *(uint32_t*)(dst + 132) = lp1;
        }
    }
    if (tid < 128) ((float*)(sm + QG_SB))[tid] = bias[tid] * scale;
    __syncthreads();

    const int wr0 = (wid & 3) << 4;        // warp row offset (0..48)
    const int jg  = (wid >> 2) << 3;       // warp j-tile offset (0 or 8)

    uint32_t aF[4][2][4];
    {
        const uint32_t qb = smb + QG_SMX + (wr0 + (lane & 15)) * XROW + ((lane >> 4) << 4);
#pragma unroll
        for (int s = 0; s < 4; s++)
#pragma unroll
            for (int p = 0; p < 2; p++)
                ldsm_x4(aF[s][p], qb + p * 128 + s * 32);
    }

    float acc[8][4];
#pragma unroll
    for (int jj = 0; jj < 8; jj++)
#pragma unroll
        for (int q = 0; q < 4; q++) acc[jj][q] = 0.f;

#pragma unroll
    for (int jj = 0; jj < 8; jj++) {
        const int j = jg + jj;
        const uint32_t kb = smb + QG_SMW + (j * 8 + (lane & 7)) * XROW + ((lane >> 3) << 4);
        uint32_t bh0[4], bh1[4], bl0[4], bl1[4];
        ldsm_x4(bh0, kb);
        ldsm_x4(bh1, kb + 64);
        ldsm_x4(bl0, kb + 128);
        ldsm_x4(bl1, kb + 192);
#pragma unroll
        for (int s = 0; s < 4; s++) {
            const uint32_t* bh = (s < 2) ? (bh0 + 2 * s) : (bh1 + 2 * (s - 2));
            const uint32_t* bl = (s < 2) ? (bl0 + 2 * s) : (bl1 + 2 * (s - 2));
            mma_f16(acc[jj], aF[s][0], bh);
            mma_f16(acc[jj], aF[s][0], bl);
            mma_f16(acc[jj], aF[s][1], bh);
        }
    }

    const float* sb = (const float*)(sm + QG_SB);
    const int ra = n0 + wr0 + (lane >> 2);
    __half* gout = isQ ? g_Qh : g_Kh;
    const size_t base = ((size_t)(b * (isQ ? NODES : UDIM) + ra)) * 256;
#pragma unroll
    for (int jj = 0; jj < 8; jj++) {
        const int j = jg + jj;
        const int c0 = j * 8 + (lane & 3) * 2;
        const float b0 = sb[c0], b1 = sb[c0 + 1];
        const int o = ((c0 >> 5) << 6) + (c0 & 31);
#pragma unroll
        for (int rr = 0; rr < 2; rr++) {
            float v0 = fmaf(acc[jj][2 * rr],     scale, b0);
            float v1 = fmaf(acc[jj][2 * rr + 1], scale, b1);
            uint32_t hp, lp;
            split2(v0, v1, hp, lp);
            __half* dst = gout + base + (size_t)rr * 8 * 256 + o;
            *(uint32_t*)dst        = hp;
            *(uint32_t*)(dst + 32) = lp;
        }
    }
}

// ---------------------------------------------------------------------------
// Kernel 2: score kernel (R14-proven EXACTLY). 256 blocks x 64 n-rows,
// 2 blocks/SM, 16 chunks of 64u, zero-fill (4 streaming rows/chunk) hidden.
// ---------------------------------------------------------------------------
#define SKROW   528
#define SMQ     0                      // 64*528 = 33792
#define SMK     33792                  // 2 * 64*528 = 67584
#define KBUF    (64 * SKROW)
#define SC_SMEM 101376

__device__ __forceinline__ void fillK_async(uint32_t smb, int b, int ustart, int buf, int tid) {
    const char* src = (const char*)(g_Kh + ((size_t)(b * UDIM + ustart)) * 256);
    const uint32_t dst = smb + SMK + buf * KBUF;
#pragma unroll
    for (int it = 0; it < 8; it++) {
        int idx = it * 256 + tid;
        int row = idx >> 5, j = idx & 31;
        CP16(dst + row * SKROW + j * 16, src + row * 512 + j * 16);
    }
}

__global__ void __launch_bounds__(256, 2) score_kernel(
    const float* __restrict__ mlp_w, const float* __restrict__ mlp_b,
    float* __restrict__ out)
{
    extern __shared__ __align__(16) char sm[];
    const uint32_t smb = smem_u32(sm);
    const int tid = threadIdx.x, lane = tid & 31, wid = tid >> 5;
    const int wr0 = (wid & 3) << 4;
    const int uw0 = (wid >> 2) << 4;
    const int b  = blockIdx.x >> 5;
    const int n0 = (blockIdx.x & 31) << 6;

    {
        const char* qsrc = (const char*)(g_Qh + ((size_t)(b * NODES + n0)) * 256);
#pragma unroll
        for (int it = 0; it < 8; it++) {
            int idx = it * 256 + tid;
            int row = idx >> 5, j = idx & 31;
            CP16(smb + SMQ + row * SKROW + j * 16, qsrc + row * 512 + j * 16);
        }
    }
    fillK_async(smb, b, 0, 0, tid);
    CPCOMMIT();

    float mm[4][4], mb_[4];
#pragma unroll
    for (int o = 0; o < 4; o++) {
        mb_[o] = mlp_b[o];
#pragma unroll
        for (int h = 0; h < 4; h++) mm[o][h] = mlp_w[o * 4 + h];
    }
    CPWAIT0();
    __syncthreads();

    uint32_t aF[4][2][2][4];
    {
        const char* qb = sm + SMQ + (wr0 + (lane >> 2)) * SKROW;
#pragma unroll
        for (int h = 0; h < 4; h++)
#pragma unroll
            for (int p = 0; p < 2; p++)
#pragma unroll
                for (int s = 0; s < 2; s++) {
                    int off = (h * 64 + p * 32 + s * 16 + (lane & 3) * 2) * 2;
                    aF[h][p][s][0] = *(const uint32_t*)(qb + off);
                    aF[h][p][s][1] = *(const uint32_t*)(qb + off + 8 * SKROW);
                    aF[h][p][s][2] = *(const uint32_t*)(qb + off + 16);
                    aF[h][p][s][3] = *(const uint32_t*)(qb + off + 8 * SKROW + 16);
                }
    }

    for (int ck = 0; ck < 16; ck++) {
        const int buf = ck & 1;
        CPWAIT0();
        __syncthreads();
        if (ck + 1 < 16) { fillK_async(smb, b, (ck + 1) * 64, buf ^ 1, tid); CPCOMMIT(); }

        // zero-fill 4 of this block's 64 output rows (streaming, hidden)
        {
            const int zr = ck * 4 + (tid >> 6);
            float4* zrow = (float4*)(out + ((size_t)(b * NODES + n0 + zr)) * NODES);
            const float4 z4 = make_float4(0.f, 0.f, 0.f, 0.f);
#pragma unroll
            for (int i = 0; i < 8; i++) __stcs(zrow + i * 64 + (tid & 63), z4);
        }

#pragma unroll
        for (int h2 = 0; h2 < 2; h2++) {
            float acc[2][4][4];
#pragma unroll
            for (int ut = 0; ut < 2; ut++)
#pragma unroll
                for (int h = 0; h < 4; h++)
#pragma unroll
                    for (int q = 0; q < 4; q++) acc[ut][h][q] = 0.f;

#pragma unroll
            for (int ut = 0; ut < 2; ut++) {
                const uint32_t kb = smb + SMK + buf * KBUF +
                                    (h2 * 32 + uw0 + ut * 8 + (lane & 7)) * SKROW +
                                    ((lane >> 3) << 4);
#pragma unroll
                for (int h = 0; h < 4; h++) {
                    uint32_t bh[4], bl[4];
                    ldsm_x4(bh, kb + h * 128);
                    ldsm_x4(bl, kb + h * 128 + 64);
#pragma unroll
                    for (int s = 0; s < 2; s++) {
                        mma_f16(acc[ut][h], aF[h][0][s], bh + 2 * s);   // hh
                        mma_f16(acc[ut][h], aF[h][0][s], bl + 2 * s);   // hl
                        mma_f16(acc[ut][h], aF[h][1][s], bh + 2 * s);   // lh
                    }
                }
            }

            const int u0 = ck * 64 + h2 * 32;
#pragma unroll
            for (int ut = 0; ut < 2; ut++) {
                float s_[4];
#pragma unroll
                for (int q = 0; q < 4; q++) {
                    float a0 = acc[ut][0][q], a1 = acc[ut][1][q];
                    float a2 = acc[ut][2][q], a3 = acc[ut][3][q];
                    float s = a0 + a1 + a2 + a3;
#pragma unroll
                    for (int o = 0; o < 4; o++) {
                        float z = fmaf(mm[o][0], a0, fmaf(mm[o][1], a1,
                                  fmaf(mm[o][2], a2, fmaf(mm[o][3], a3, mb_[o]))));
                        s += fmaxf(z, 0.f);
                    }
                    s_[q] = s;
                }
                float* sg = g_S + ((size_t)(b * NODES + n0 + wr0 + (lane >> 2))) * UDIM
                            + u0 + uw0 + ut * 8 + (lane & 3) * 2;
                *(float2*)sg              = make_float2(s_[0], s_[1]);
                *(float2*)(sg + 8 * UDIM) = make_float2(s_[2], s_[3]);
            }
        }
    }
}

// ---------------------------------------------------------------------------
// Kernel 3: top-32 per row, radix select (R14-proven).
// ---------------------------------------------------------------------------
__global__ void __launch_bounds__(256, 4) topk_kernel(float* __restrict__ out)
{
    const int w = threadIdx.x >> 5, lane = threadIdx.x & 31;
    const int row = blockIdx.x * 8 + w;
    __shared__ unsigned hist[8][256];
    __shared__ unsigned tie_idx[8][64];
    __shared__ unsigned found[8][2];
    __shared__ unsigned tie_cnt[8];

    const float4* srow4 = (const float4*)(g_S + (size_t)row * UDIM);
    unsigned keys[32];
#pragma unroll
    for (int i = 0; i < 8; i++) {
        float4 v = srow4[i * 32 + lane];
        const float f[4] = {v.x, v.y, v.z, v.w};
#pragma unroll
        for (int c = 0; c < 4; c++) {
            unsigned u = __float_as_uint(f[c]);
            keys[i * 4 + c] = u ^ (((unsigned)((int)u >> 31)) | 0x80000000u);
        }
    }

    unsigned prefix = 0;
    int needed = NNB;
    for (int shift = 24; shift >= 0; shift -= 8) {
        for (int t = lane; t < 256; t += 32) hist[w][t] = 0;
        __syncwarp();
        const unsigned hm = (shift == 24) ? 0u : (0xFFFFFFFFu << (shift + 8));
#pragma unroll
        for (int j = 0; j < 32; j++)
            if (((keys[j] ^ prefix) & hm) == 0)
                atomicAdd(&hist[w][(keys[j] >> shift) & 255], 1u);
        __syncwarp();
        unsigned s = 0;
#pragma unroll
        for (int t = 0; t < 8; t++) s += hist[w][lane * 8 + t];
        unsigned rs = s;
#pragma unroll
        for (int off = 1; off < 32; off <<= 1) {
            unsigned v = __shfl_down_sync(0xffffffffu, rs, off);
            if (lane + off < 32) rs += v;
        }
        unsigned acc = rs - s;
        for (int t = 7; t >= 0; t--) {
            unsigned c = hist[w][lane * 8 + t];
            if ((int)acc < needed && needed <= (int)(acc + c)) {
                found[w][0] = (unsigned)(lane * 8 + t);
                found[w][1] = acc;
            }
            acc += c;
        }
        __syncwarp();
        prefix |= found[w][0] << shift;
        needed -= (int)found[w][1];
        __syncwarp();
    }

    const int b = row >> 11, n = row & 2047;
    float* orow = out + ((size_t)b * NODES + n) * (size_t)NODES;
    if (lane == 0) tie_cnt[w] = 0;
    __syncwarp();
#pragma unroll
    for (int j = 0; j < 32; j++) {
        const unsigned elem = (unsigned)((j >> 2) * 128 + lane * 4 + (j & 3));
        if (keys[j] > prefix) orow[elem] = key2val(keys[j]);
        else if (keys[j] == prefix) {
            unsigned p = atomicAdd(&tie_cnt[w], 1u);
            if (p < 64) tie_idx[w][p] = elem;
        }
    }
    __syncwarp();
    if (lane == 0) {
        int cnt = tie_cnt[w] < 64 ? (int)tie_cnt[w] : 64;
        float kval = key2val(prefix);
        for (int e = 0; e < needed; e++) {
            int bi = -1; unsigned bidx = 0xFFFFFFFFu;
            for (int t = 0; t < cnt; t++)
                if (tie_idx[w][t] < bidx) { bidx = tie_idx[w][t]; bi = t; }
            if (bi >= 0) { orow[bidx] = kval; tie_idx[w][bi] = 0xFFFFFFFFu; }
        }
    }
}

// ---------------------------------------------------------------------------
extern "C" void kernel_launch(void* const* d_in, const int* in_sizes, int n_in,
                              void* d_out, int out_size)
{
    const float* x     = (const float*)d_in[0];
    const float* Wq    = (const float*)d_in[1];
    const float* bq    = (const float*)d_in[2];
    const float* Wk    = (const float*)d_in[3];
    const float* bk    = (const float*)d_in[4];
    const float* mlp_w = (const float*)d_in[5];
    const float* mlp_b = (const float*)d_in[6];

    float* out = (float*)d_out;

    cudaFuncSetAttribute(qkgemm_kernel,
                         cudaFuncAttributeMaxDynamicSharedMemorySize, QG_SMEM);
    qkgemm_kernel<<<384, 256, QG_SMEM>>>(x, Wq, bq, Wk, bk);

    cudaFuncSetAttribute(score_kernel,
                         cudaFuncAttributeMaxDynamicSharedMemorySize, SC_SMEM);
    score_kernel<<<256, 256, SC_SMEM>>>(mlp_w, mlp_b, out);

    topk_kernel<<<BATCH * NODES / 8, 256>>>(out);
}